// round 2
// baseline (speedup 1.0000x reference)
#include <cuda_runtime.h>

// WeightedLoss: mean over 64M elems of (target==1 ? 1-sigmoid(pred) : 0.1)
// 1 - sigmoid(x) = sigmoid(-x) = 1/(1 + e^x)
//
// Single-kernel HBM-streaming reduction (512 MiB read).
// Last-block-done pattern fuses the final reduce (removes 4.4us 2nd launch).
// Deterministic: partial order fixed, final sum order fixed.

#define NBLOCKS 2048
#define NTHREADS 256

__device__ float g_partials[NBLOCKS];
__device__ unsigned int g_arrive = 0;   // reset to 0 by the last block each run

__global__ __launch_bounds__(NTHREADS)
void wl_fused_kernel(const float* __restrict__ pred,
                     const int* __restrict__ tgt,
                     int n, float inv_n,
                     float* __restrict__ out)
{
    const float4* __restrict__ p4 = reinterpret_cast<const float4*>(pred);
    const int4*   __restrict__ t4 = reinterpret_cast<const int4*>(tgt);
    const int n4 = n >> 2;  // 64M divisible by 4

    float acc = 0.0f;
    const int stride = gridDim.x * blockDim.x;
    for (int i = blockIdx.x * blockDim.x + threadIdx.x; i < n4; i += stride) {
        // streaming loads: no reuse, evict-first keeps L2 clean
        float4 p = __ldcs(&p4[i]);
        int4   t = __ldcs(&t4[i]);
        // sigmoid(-p) = 1/(1+e^p); __expf overflow->inf, __fdividef->0 (correct limit)
        float s0 = __fdividef(1.0f, 1.0f + __expf(p.x));
        float s1 = __fdividef(1.0f, 1.0f + __expf(p.y));
        float s2 = __fdividef(1.0f, 1.0f + __expf(p.z));
        float s3 = __fdividef(1.0f, 1.0f + __expf(p.w));
        acc += (t.x == 1) ? s0 : 0.1f;
        acc += (t.y == 1) ? s1 : 0.1f;
        acc += (t.z == 1) ? s2 : 0.1f;
        acc += (t.w == 1) ? s3 : 0.1f;
    }

    // intra-block reduce
    #pragma unroll
    for (int o = 16; o > 0; o >>= 1)
        acc += __shfl_xor_sync(0xffffffffu, acc, o);

    __shared__ float sw[NTHREADS / 32];
    __shared__ bool s_last;
    if ((threadIdx.x & 31) == 0) sw[threadIdx.x >> 5] = acc;
    __syncthreads();

    if (threadIdx.x < 32) {
        float v = (threadIdx.x < NTHREADS / 32) ? sw[threadIdx.x] : 0.0f;
        #pragma unroll
        for (int o = 4; o > 0; o >>= 1)
            v += __shfl_xor_sync(0xffffffffu, v, o);
        if (threadIdx.x == 0) {
            g_partials[blockIdx.x] = v;
            __threadfence();
            unsigned int prev = atomicAdd(&g_arrive, 1u);
            s_last = (prev == (unsigned int)(gridDim.x - 1));
        }
    }
    __syncthreads();

    // last block to arrive performs the final reduction (fixed order: deterministic)
    if (s_last) {
        float a = 0.0f;
        for (int i = threadIdx.x; i < NBLOCKS; i += NTHREADS)
            a += g_partials[i];   // 8 per thread, fixed order

        #pragma unroll
        for (int o = 16; o > 0; o >>= 1)
            a += __shfl_xor_sync(0xffffffffu, a, o);

        __shared__ float sw2[NTHREADS / 32];
        if ((threadIdx.x & 31) == 0) sw2[threadIdx.x >> 5] = a;
        __syncthreads();

        if (threadIdx.x < 32) {
            float v = (threadIdx.x < NTHREADS / 32) ? sw2[threadIdx.x] : 0.0f;
            #pragma unroll
            for (int o = 4; o > 0; o >>= 1)
                v += __shfl_xor_sync(0xffffffffu, v, o);
            if (threadIdx.x == 0) {
                out[0] = v * inv_n;
                __threadfence();
                g_arrive = 0;   // re-arm for next graph replay
            }
        }
    }
}

extern "C" void kernel_launch(void* const* d_in, const int* in_sizes, int n_in,
                              void* d_out, int out_size)
{
    const float* pred = (const float*)d_in[0];
    const int*   tgt  = (const int*)d_in[1];
    float*       out  = (float*)d_out;
    const int n = in_sizes[0];

    wl_fused_kernel<<<NBLOCKS, NTHREADS>>>(pred, tgt, n, 1.0f / (float)n, out);
}

// round 3
// speedup vs baseline: 1.0505x; 1.0505x over previous
#include <cuda_runtime.h>

// WeightedLoss: mean over 64M elems of (target==1 ? 1-sigmoid(pred) : 0.1)
// 1 - sigmoid(x) = sigmoid(-x) = 1/(1 + e^x)
//
// Single fused kernel, 512 MiB HBM stream.
// R2 lesson: __ldcs cost ~10% bandwidth on sm_103a -> plain LDG.E.128.
// Grid = 148 SMs * 8 blocks = fully-resident single wave.
// Last-block-done final reduce (deterministic, fixed order).

#define NBLOCKS (148 * 8)
#define NTHREADS 256

__device__ float g_partials[NBLOCKS];
__device__ unsigned int g_arrive = 0;   // re-armed to 0 by the last block each run

__global__ __launch_bounds__(NTHREADS)
void wl_fused_kernel(const float* __restrict__ pred,
                     const int* __restrict__ tgt,
                     int n, float inv_n,
                     float* __restrict__ out)
{
    const float4* __restrict__ p4 = reinterpret_cast<const float4*>(pred);
    const int4*   __restrict__ t4 = reinterpret_cast<const int4*>(tgt);
    const int n4 = n >> 2;  // 64M divisible by 4

    float acc = 0.0f;
    const int stride = gridDim.x * blockDim.x;
    for (int i = blockIdx.x * blockDim.x + threadIdx.x; i < n4; i += stride) {
        float4 p = p4[i];           // plain LDG.E.128 — fastest stream path on B300
        int4   t = t4[i];
        // sigmoid(-p) = 1/(1+e^p); __expf overflow->inf, __fdividef->0 (correct limit)
        float s0 = __fdividef(1.0f, 1.0f + __expf(p.x));
        float s1 = __fdividef(1.0f, 1.0f + __expf(p.y));
        float s2 = __fdividef(1.0f, 1.0f + __expf(p.z));
        float s3 = __fdividef(1.0f, 1.0f + __expf(p.w));
        acc += (t.x == 1) ? s0 : 0.1f;
        acc += (t.y == 1) ? s1 : 0.1f;
        acc += (t.z == 1) ? s2 : 0.1f;
        acc += (t.w == 1) ? s3 : 0.1f;
    }

    // intra-block reduce
    #pragma unroll
    for (int o = 16; o > 0; o >>= 1)
        acc += __shfl_xor_sync(0xffffffffu, acc, o);

    __shared__ float sw[NTHREADS / 32];
    __shared__ bool s_last;
    if ((threadIdx.x & 31) == 0) sw[threadIdx.x >> 5] = acc;
    __syncthreads();

    if (threadIdx.x < 32) {
        float v = (threadIdx.x < NTHREADS / 32) ? sw[threadIdx.x] : 0.0f;
        #pragma unroll
        for (int o = 4; o > 0; o >>= 1)
            v += __shfl_xor_sync(0xffffffffu, v, o);
        if (threadIdx.x == 0) {
            g_partials[blockIdx.x] = v;
            __threadfence();
            unsigned int prev = atomicAdd(&g_arrive, 1u);
            s_last = (prev == (unsigned int)(gridDim.x - 1));
        }
    }
    __syncthreads();

    // last block performs the final reduction (fixed order: deterministic)
    if (s_last) {
        float a = 0.0f;
        for (int i = threadIdx.x; i < NBLOCKS; i += NTHREADS)
            a += g_partials[i];

        #pragma unroll
        for (int o = 16; o > 0; o >>= 1)
            a += __shfl_xor_sync(0xffffffffu, a, o);

        __shared__ float sw2[NTHREADS / 32];
        if ((threadIdx.x & 31) == 0) sw2[threadIdx.x >> 5] = a;
        __syncthreads();

        if (threadIdx.x < 32) {
            float v = (threadIdx.x < NTHREADS / 32) ? sw2[threadIdx.x] : 0.0f;
            #pragma unroll
            for (int o = 4; o > 0; o >>= 1)
                v += __shfl_xor_sync(0xffffffffu, v, o);
            if (threadIdx.x == 0) {
                out[0] = v * inv_n;
                __threadfence();
                g_arrive = 0;   // re-arm for next graph replay
            }
        }
    }
}

extern "C" void kernel_launch(void* const* d_in, const int* in_sizes, int n_in,
                              void* d_out, int out_size)
{
    const float* pred = (const float*)d_in[0];
    const int*   tgt  = (const int*)d_in[1];
    float*       out  = (float*)d_out;
    const int n = in_sizes[0];

    wl_fused_kernel<<<NBLOCKS, NTHREADS>>>(pred, tgt, n, 1.0f / (float)n, out);
}